// round 3
// baseline (speedup 1.0000x reference)
#include <cuda_runtime.h>
#include <cuda_bf16.h>
#include <cstdint>
#include <cstddef>

using bf16 = __nv_bfloat16;

#define DI __device__ __forceinline__

// ---------------- constants ----------------
// V=32000, E=512, D=1024, 2E=1024, B=32, S=64, T=48
static constexpr int Vv = 32000;
static constexpr int Ee = 512;
static constexpr int Dd = 1024;
static constexpr int E2 = 1024;
static constexpr int Bb = 32;
static constexpr int Ss = 64;
static constexpr int Tt = 48;

// ---------------- scratch layout ----------------
constexpr size_t O_ENC_H   = 0;
constexpr size_t O_ENC_L   = O_ENC_H   + (size_t)2048*1024*2;
constexpr size_t O_ATTNS   = O_ENC_L   + (size_t)2048*1024*2;
constexpr size_t O_WPROJ_H = O_ATTNS   + (size_t)2048*1024*4;
constexpr size_t O_WPROJ_L = O_WPROJ_H + (size_t)1024*1024*2;
constexpr size_t O_WWORD_H = O_WPROJ_L + (size_t)1024*1024*2;
constexpr size_t O_WWORD_L = O_WWORD_H + (size_t)4096*512*2;
constexpr size_t O_WCAT_H  = O_WWORD_L + (size_t)4096*512*2;
constexpr size_t O_WCAT_L  = O_WCAT_H  + (size_t)4096*2048*2;
constexpr size_t O_W1_H    = O_WCAT_L  + (size_t)4096*2048*2;
constexpr size_t O_W1_L    = O_W1_H    + (size_t)4096*1024*2;
constexpr size_t O_WCOMB_H = O_W1_L    + (size_t)4096*1024*2;
constexpr size_t O_WCOMB_L = O_WCOMB_H + (size_t)1024*2048*2;
constexpr size_t O_WOUT_H  = O_WCOMB_L + (size_t)1024*2048*2;
constexpr size_t O_WOUT_L  = O_WOUT_H  + (size_t)32000*1024*2;
constexpr size_t O_BIAS0   = O_WOUT_L  + (size_t)32000*1024*2;
constexpr size_t O_BIAS1   = O_BIAS0   + (size_t)4096*4;
constexpr size_t O_AEMB_H  = O_BIAS1   + (size_t)4096*4;
constexpr size_t O_AEMB_L  = O_AEMB_H  + (size_t)1536*512*2;
constexpr size_t O_GWORD   = O_AEMB_L  + (size_t)1536*512*2;
constexpr size_t O_X_H     = O_GWORD   + (size_t)1536*4096*4;
constexpr size_t O_X_L     = O_X_H     + (size_t)32*2048*2;
constexpr size_t O_Y_H     = O_X_L     + (size_t)32*2048*2;
constexpr size_t O_Y_L     = O_Y_H     + (size_t)32*2048*2;
constexpr size_t O_HMID_H  = O_Y_L     + (size_t)32*2048*2;
constexpr size_t O_HMID_L  = O_HMID_H  + (size_t)32*1024*2;
constexpr size_t O_HF32    = O_HMID_L  + (size_t)32*1024*2;
constexpr size_t O_CPREV   = O_HF32    + (size_t)32*1024*4;
constexpr size_t O_CMID    = O_CPREV   + (size_t)32*1024*4;
constexpr size_t O_AV_H    = O_CMID    + (size_t)32*1024*4;
constexpr size_t O_AV_L    = O_AV_H    + (size_t)1536*1024*2;
constexpr size_t SCRATCH_BYTES = O_AV_L + (size_t)1536*1024*2;

__device__ __align__(1024) unsigned char g_scratch[SCRATCH_BYTES];

// ---------------- helpers ----------------
DI float sigmoidf_(float x){ return 1.0f/(1.0f+expf(-x)); }

DI void split_store(float v, bf16* ph, bf16* pl){
    bf16 h = __float2bfloat16(v);
    *ph = h;
    *pl = __float2bfloat16(v - __bfloat162float(h));
}

DI void cpasync16(void* sdst, const void* gsrc){
    uint32_t sa = (uint32_t)__cvta_generic_to_shared(sdst);
    asm volatile("cp.async.cg.shared.global [%0], [%1], 16;\n" :: "r"(sa), "l"(gsrc));
}
DI void cpcommit(){ asm volatile("cp.async.commit_group;\n"); }
DI void cpwait1(){ asm volatile("cp.async.wait_group 1;\n"); }

DI void mma_bf16(float* c, const uint32_t* a, const uint32_t* b){
    asm volatile(
        "mma.sync.aligned.m16n8k16.row.col.f32.bf16.bf16.f32 "
        "{%0,%1,%2,%3}, {%4,%5,%6,%7}, {%8,%9}, {%0,%1,%2,%3};\n"
        : "+f"(c[0]), "+f"(c[1]), "+f"(c[2]), "+f"(c[3])
        : "r"(a[0]), "r"(a[1]), "r"(a[2]), "r"(a[3]), "r"(b[0]), "r"(b[1]));
}

// ---------------- prep kernels ----------------
__global__ void k_split_plain(const float* __restrict__ src, bf16* __restrict__ h,
                              bf16* __restrict__ l, size_t n){
    for (size_t i = (size_t)blockIdx.x*blockDim.x + threadIdx.x; i < n;
         i += (size_t)gridDim.x*blockDim.x)
        split_store(src[i], h+i, l+i);
}

// enc [b*64+s][k] <- src_encodings[s][b][k]
__global__ void k_split_enc(const float* __restrict__ src, bf16* __restrict__ h,
                            bf16* __restrict__ l){
    size_t n = (size_t)2048*1024;
    for (size_t i = (size_t)blockIdx.x*blockDim.x + threadIdx.x; i < n;
         i += (size_t)gridDim.x*blockDim.x){
        int r = (int)(i >> 10), k = (int)(i & 1023);
        int b = r >> 6, s = r & 63;
        float v = src[((size_t)(s*Bb + b))*1024 + k];
        split_store(v, h+i, l+i);
    }
}

// permuted row r = 4*ch + gate ; source row = gate*1024 + ch
DI int perm_src_row(int r){ return (r & 3)*1024 + (r >> 2); }

__global__ void k_build_wword(const float* __restrict__ Wih0, bf16* __restrict__ h,
                              bf16* __restrict__ l){
    size_t n = (size_t)4096*512;
    for (size_t i = (size_t)blockIdx.x*blockDim.x + threadIdx.x; i < n;
         i += (size_t)gridDim.x*blockDim.x){
        int r = (int)(i >> 9), k = (int)(i & 511);
        float v = Wih0[(size_t)perm_src_row(r)*1536 + k];
        split_store(v, h+i, l+i);
    }
}

__global__ void k_build_wcat(const float* __restrict__ Wih0, const float* __restrict__ Whh0,
                             bf16* __restrict__ h, bf16* __restrict__ l){
    size_t n = (size_t)4096*2048;
    for (size_t i = (size_t)blockIdx.x*blockDim.x + threadIdx.x; i < n;
         i += (size_t)gridDim.x*blockDim.x){
        int r = (int)(i >> 11), k = (int)(i & 2047);
        int sr = perm_src_row(r);
        float v = (k < 1024) ? Wih0[(size_t)sr*1536 + 512 + k]
                             : Whh0[(size_t)sr*1024 + (k-1024)];
        split_store(v, h+i, l+i);
    }
}

__global__ void k_build_w1(const float* __restrict__ Wih1, const float* __restrict__ Whh1,
                           bf16* __restrict__ h, bf16* __restrict__ l){
    size_t n = (size_t)4096*1024;
    for (size_t i = (size_t)blockIdx.x*blockDim.x + threadIdx.x; i < n;
         i += (size_t)gridDim.x*blockDim.x){
        int r = (int)(i >> 10), k = (int)(i & 1023);
        int sr = perm_src_row(r);
        float v = Wih1[(size_t)sr*1024 + k] + Whh1[(size_t)sr*1024 + k];
        split_store(v, h+i, l+i);
    }
}

__global__ void k_build_bias(const float* __restrict__ bi0, const float* __restrict__ bh0,
                             const float* __restrict__ bi1, const float* __restrict__ bh1,
                             float* __restrict__ o0, float* __restrict__ o1){
    int r = blockIdx.x*blockDim.x + threadIdx.x;
    if (r < 4096){
        int sr = perm_src_row(r);
        o0[r] = bi0[sr] + bh0[sr];
        o1[r] = bi1[sr] + bh1[sr];
    }
}

__global__ void k_gather_emb(const float* __restrict__ emb, const int* __restrict__ tgt,
                             bf16* __restrict__ h, bf16* __restrict__ l){
    size_t n = (size_t)1536*512;
    for (size_t i = (size_t)blockIdx.x*blockDim.x + threadIdx.x; i < n;
         i += (size_t)gridDim.x*blockDim.x){
        int m = (int)(i >> 9), k = (int)(i & 511);
        float v = emb[(size_t)tgt[m]*512 + k];
        split_store(v, h+i, l+i);
    }
}

__global__ void k_init_state(const float* __restrict__ h0, const float* __restrict__ c0,
                             float* __restrict__ cprev, bf16* __restrict__ Xh,
                             bf16* __restrict__ Xl){
    int i = blockIdx.x*blockDim.x + threadIdx.x;
    if (i < 32*1024){
        int row = i >> 10, k = i & 1023;
        cprev[i] = c0[i];
        bf16 z = __float2bfloat16(0.0f);
        Xh[row*2048 + k] = z;
        Xl[row*2048 + k] = z;
        split_store(h0[i], Xh + row*2048 + 1024 + k, Xl + row*2048 + 1024 + k);
    }
}

// ---------------- attention kernel ----------------
__global__ void k_attention(const float* __restrict__ attnS,   // [2048,1024], row=b*64+s
                            const float* __restrict__ hf,      // [32,1024]
                            const float* __restrict__ src,     // [64,32,1024]
                            bf16* __restrict__ Yh, bf16* __restrict__ Yl){ // [32,2048]
    int b = blockIdx.x;
    int tid = threadIdx.x, w = tid >> 5, lane = tid & 31;
    __shared__ float sh[1024];
    __shared__ float salpha[64];
    __shared__ float sinv;

    for (int i = tid; i < 1024; i += 256) sh[i] = hf[b*1024 + i];
    __syncthreads();

    for (int s = w; s < 64; s += 8){
        const float* row = attnS + (size_t)(b*64 + s)*1024;
        float acc = 0.f;
        #pragma unroll 4
        for (int k = lane; k < 1024; k += 32) acc += row[k]*sh[k];
        #pragma unroll
        for (int o = 16; o > 0; o >>= 1) acc += __shfl_xor_sync(0xffffffffu, acc, o);
        if (lane == 0) salpha[s] = acc;  // raw logits for now
    }
    __syncthreads();
    if (tid == 0){
        float m = -1e30f;
        #pragma unroll
        for (int s = 0; s < 64; s++) m = fmaxf(m, salpha[s]);
        float su = 0.f;
        #pragma unroll
        for (int s = 0; s < 64; s++){ float e = expf(salpha[s]-m); salpha[s] = e; su += e; }
        sinv = 1.0f/su;
    }
    __syncthreads();
    float inv = sinv;
    for (int e = tid; e < 1024; e += 256){
        float acc = 0.f;
        #pragma unroll 8
        for (int s = 0; s < 64; s++)
            acc += salpha[s]*src[((size_t)(s*Bb + b))*1024 + e];
        acc *= inv;
        split_store(acc, Yh + b*2048 + 1024 + e, Yl + b*2048 + 1024 + e);
    }
}

// ---------------- 3-pass split-bf16 GEMM ----------------
// C[M,N] = A[M,K] * B[N,K]^T  with A ~ Ah+Al, B ~ Bh+Bl (3 mma passes).
// epi: 0=store, 1=store+bias, 2=LSTM cell (interleaved gates), 3=tanh+split
template<int BM, int BN, int BK, int WM, int WN>
__global__ void __launch_bounds__(32*(BM/WM)*(BN/WN))
gemm3(const bf16* __restrict__ Ah, const bf16* __restrict__ Al, int lda,
      const bf16* __restrict__ Bh, const bf16* __restrict__ Bl, int ldb,
      float* __restrict__ C, int ldc,
      int M, int N, int K, int epi,
      const float* __restrict__ addend,  // [M,N] ld=N (epi2) or null
      const float* __restrict__ bias,    // [N] or null
      const float* __restrict__ cin, float* __restrict__ cout,
      bf16* __restrict__ h1h, bf16* __restrict__ h1l, int h1ld,
      bf16* __restrict__ h2h, bf16* __restrict__ h2l, int h2ld,
      float* __restrict__ hf32,
      bf16* __restrict__ o2h, bf16* __restrict__ o2l, int o2ld, int o2r0)
{
    constexpr int WARPS_M = BM/WM, WARPS_N = BN/WN;
    constexpr int THREADS = 32*WARPS_M*WARPS_N;
    constexpr int MF = WM/16, NF = WN/8;
    constexpr int BKP = BK + 8;          // bf16 elems per smem row (pad)
    constexpr int WRD = BKP/2;           // 32-bit words per row
    constexpr int ASZ = BM*BKP, BSZ = BN*BKP;
    constexpr int STG = 2*ASZ + 2*BSZ;   // elems per stage
    extern __shared__ bf16 smem[];

    const int tid = threadIdx.x, wid = tid >> 5, lane = tid & 31;
    const int wm = wid / WARPS_N, wn = wid % WARPS_N;
    const int g = lane >> 2, t = lane & 3;
    const int bm0 = blockIdx.x*BM, bn0 = blockIdx.y*BN;

    float acc[MF][NF][4];
    #pragma unroll
    for (int a = 0; a < MF; a++)
        #pragma unroll
        for (int b = 0; b < NF; b++)
            #pragma unroll
            for (int c = 0; c < 4; c++) acc[a][b][c] = 0.f;

    const int KT = K/BK;

    auto load_tile = [&](int kt, int st){
        bf16* s = smem + st*STG;
        int k0 = kt*BK;
        for (int c = tid; c < BM*4; c += THREADS){
            int r = c >> 2, cc = c & 3;
            size_t go = (size_t)(bm0 + r)*lda + k0 + cc*8;
            cpasync16(s + r*BKP + cc*8, Ah + go);
            cpasync16(s + ASZ + r*BKP + cc*8, Al + go);
        }
        for (int c = tid; c < BN*4; c += THREADS){
            int r = c >> 2, cc = c & 3;
            size_t go = (size_t)(bn0 + r)*ldb + k0 + cc*8;
            cpasync16(s + 2*ASZ + r*BKP + cc*8, Bh + go);
            cpasync16(s + 2*ASZ + BSZ + r*BKP + cc*8, Bl + go);
        }
    };

    load_tile(0, 0); cpcommit();
    if (KT > 1) load_tile(1, 1);
    cpcommit();

    for (int kt = 0; kt < KT; kt++){
        cpwait1();
        __syncthreads();
        const bf16* s = smem + (kt & 1)*STG;
        const uint32_t* sAh = (const uint32_t*)s;
        const uint32_t* sAl = (const uint32_t*)(s + ASZ);
        const uint32_t* sBh = (const uint32_t*)(s + 2*ASZ);
        const uint32_t* sBl = (const uint32_t*)(s + 2*ASZ + BSZ);
        #pragma unroll
        for (int ks = 0; ks < BK/16; ks++){
            uint32_t af[MF][4], alf[MF][4], bhf[NF][2], blf[NF][2];
            #pragma unroll
            for (int mf = 0; mf < MF; mf++){
                int r0 = wm*WM + mf*16;
                int i0 = (r0 + g)*WRD + ks*8 + t;
                int i1 = (r0 + g + 8)*WRD + ks*8 + t;
                af[mf][0] = sAh[i0];   af[mf][1] = sAh[i1];
                af[mf][2] = sAh[i0+4]; af[mf][3] = sAh[i1+4];
                alf[mf][0] = sAl[i0];   alf[mf][1] = sAl[i1];
                alf[mf][2] = sAl[i0+4]; alf[mf][3] = sAl[i1+4];
            }
            #pragma unroll
            for (int nf = 0; nf < NF; nf++){
                int cb = wn*WN + nf*8 + g;
                int i0 = cb*WRD + ks*8 + t;
                bhf[nf][0] = sBh[i0]; bhf[nf][1] = sBh[i0+4];
                blf[nf][0] = sBl[i0]; blf[nf][1] = sBl[i0+4];
            }
            #pragma unroll
            for (int mf = 0; mf < MF; mf++)
                #pragma unroll
                for (int nf = 0; nf < NF; nf++){
                    mma_bf16(acc[mf][nf], af[mf],  bhf[nf]);
                    mma_bf16(acc[mf][nf], alf[mf], bhf[nf]);
                    mma_bf16(acc[mf][nf], af[mf],  blf[nf]);
                }
        }
        __syncthreads();
        if (kt + 2 < KT) load_tile(kt + 2, kt & 1);
        cpcommit();
    }

    // epilogue
    #pragma unroll
    for (int mf = 0; mf < MF; mf++){
        #pragma unroll
        for (int nf = 0; nf < NF; nf++){
            #pragma unroll
            for (int half = 0; half < 2; half++){
                int row = bm0 + wm*WM + mf*16 + g + half*8;
                int col = bn0 + wn*WN + nf*8 + 2*t;
                float v0 = acc[mf][nf][half*2 + 0];
                float v1 = acc[mf][nf][half*2 + 1];
                if (epi <= 1){
                    if (epi == 1){ v0 += bias[col]; v1 += bias[col+1]; }
                    C[(size_t)row*ldc + col]     = v0;
                    C[(size_t)row*ldc + col + 1] = v1;
                } else if (epi == 2){
                    if (addend){ v0 += addend[(size_t)row*N + col];
                                 v1 += addend[(size_t)row*N + col + 1]; }
                    if (bias){ v0 += bias[col]; v1 += bias[col+1]; }
                    float w0 = __shfl_xor_sync(0xffffffffu, v0, 1);
                    float w1 = __shfl_xor_sync(0xffffffffu, v1, 1);
                    if ((t & 1) == 0){
                        // even lanes hold (i,f); partner holds (g,o)
                        float ig = sigmoidf_(v0), fg = sigmoidf_(v1);
                        float gg = tanhf(w0),    og = sigmoidf_(w1);
                        int ch = col >> 2;
                        float cn = fg*cin[row*1024 + ch] + ig*gg;
                        float hn = og*tanhf(cn);
                        cout[row*1024 + ch] = cn;
                        bf16 hh = __float2bfloat16(hn);
                        bf16 hl = __float2bfloat16(hn - __bfloat162float(hh));
                        h1h[row*h1ld + ch] = hh;
                        h1l[row*h1ld + ch] = hl;
                        if (h2h){ h2h[row*h2ld + ch] = hh; h2l[row*h2ld + ch] = hl; }
                        if (hf32) hf32[row*1024 + ch] = hn;
                    }
                } else { // epi == 3 : tanh + split to two destinations
                    float a0 = tanhf(v0), a1 = tanhf(v1);
                    bf16 p0 = __float2bfloat16(a0);
                    bf16 q0 = __float2bfloat16(a0 - __bfloat162float(p0));
                    bf16 p1 = __float2bfloat16(a1);
                    bf16 q1 = __float2bfloat16(a1 - __bfloat162float(p1));
                    h1h[row*h1ld + col]   = p0; h1l[row*h1ld + col]   = q0;
                    h1h[row*h1ld + col+1] = p1; h1l[row*h1ld + col+1] = q1;
                    o2h[(size_t)(o2r0+row)*o2ld + col]   = p0;
                    o2l[(size_t)(o2r0+row)*o2ld + col]   = q0;
                    o2h[(size_t)(o2r0+row)*o2ld + col+1] = p1;
                    o2l[(size_t)(o2r0+row)*o2ld + col+1] = q1;
                }
            }
        }
    }
}

// ---------------- host launch ----------------
static constexpr int SM_SMALL = 2*(2*(32*40) + 2*(32*40))*2;     // 20480 B
static constexpr int SM_LARGE = 2*(2*(128*40) + 2*(128*40))*2;   // 81920 B

extern "C" void kernel_launch(void* const* d_in, const int* in_sizes, int n_in,
                              void* d_out, int out_size){
    const float* src   = (const float*)d_in[0];
    const float* h0    = (const float*)d_in[1];
    const float* c0    = (const float*)d_in[2];
    const float* emb   = (const float*)d_in[3];
    const float* Wproj = (const float*)d_in[4];
    const float* Wcomb = (const float*)d_in[5];
    const float* Wout  = (const float*)d_in[6];
    const float* Wih0  = (const float*)d_in[7];
    const float* Whh0  = (const float*)d_in[8];
    const float* bih0  = (const float*)d_in[9];
    const float* bhh0  = (const float*)d_in[10];
    const float* Wih1  = (const float*)d_in[11];
    const float* Whh1  = (const float*)d_in[12];
    const float* bih1  = (const float*)d_in[13];
    const float* bhh1  = (const float*)d_in[14];
    const int*   tgt   = (const int*)d_in[15];
    float* out = (float*)d_out;

    void* basep = nullptr;
    cudaGetSymbolAddress(&basep, g_scratch);
    unsigned char* base = (unsigned char*)basep;

    bf16*  encH   = (bf16*)(base + O_ENC_H);
    bf16*  encL   = (bf16*)(base + O_ENC_L);
    float* attnS  = (float*)(base + O_ATTNS);
    bf16*  WprojH = (bf16*)(base + O_WPROJ_H);
    bf16*  WprojL = (bf16*)(base + O_WPROJ_L);
    bf16*  WwordH = (bf16*)(base + O_WWORD_H);
    bf16*  WwordL = (bf16*)(base + O_WWORD_L);
    bf16*  WcatH  = (bf16*)(base + O_WCAT_H);
    bf16*  WcatL  = (bf16*)(base + O_WCAT_L);
    bf16*  W1H    = (bf16*)(base + O_W1_H);
    bf16*  W1L    = (bf16*)(base + O_W1_L);
    bf16*  WcombH = (bf16*)(base + O_WCOMB_H);
    bf16*  WcombL = (bf16*)(base + O_WCOMB_L);
    bf16*  WoutH  = (bf16*)(base + O_WOUT_H);
    bf16*  WoutL  = (bf16*)(base + O_WOUT_L);
    float* bias0  = (float*)(base + O_BIAS0);
    float* bias1  = (float*)(base + O_BIAS1);
    bf16*  AembH  = (bf16*)(base + O_AEMB_H);
    bf16*  AembL  = (bf16*)(base + O_AEMB_L);
    float* Gword  = (float*)(base + O_GWORD);
    bf16*  XH     = (bf16*)(base + O_X_H);
    bf16*  XL     = (bf16*)(base + O_X_L);
    bf16*  YH     = (bf16*)(base + O_Y_H);
    bf16*  YL     = (bf16*)(base + O_Y_L);
    bf16*  HmidH  = (bf16*)(base + O_HMID_H);
    bf16*  HmidL  = (bf16*)(base + O_HMID_L);
    float* hf32   = (float*)(base + O_HF32);
    float* cprev  = (float*)(base + O_CPREV);
    float* cmid   = (float*)(base + O_CMID);
    bf16*  AVH    = (bf16*)(base + O_AV_H);
    bf16*  AVL    = (bf16*)(base + O_AV_L);

    cudaFuncSetAttribute((const void*)gemm3<128,128,32,64,32>,
                         cudaFuncAttributeMaxDynamicSharedMemorySize, SM_LARGE);

    // ---- setup / precompute ----
    k_split_enc<<<4096,256>>>(src, encH, encL);
    k_split_plain<<<2048,256>>>(Wproj, WprojH, WprojL, (size_t)1024*1024);
    k_split_plain<<<4096,256>>>(Wcomb, WcombH, WcombL, (size_t)1024*2048);
    k_split_plain<<<8192,256>>>(Wout, WoutH, WoutL, (size_t)32000*1024);
    k_build_wword<<<4096,256>>>(Wih0, WwordH, WwordL);
    k_build_wcat<<<8192,256>>>(Wih0, Whh0, WcatH, WcatL);
    k_build_w1<<<4096,256>>>(Wih1, Whh1, W1H, W1L);
    k_build_bias<<<16,256>>>(bih0, bhh0, bih1, bhh1, bias0, bias1);
    k_gather_emb<<<2048,256>>>(emb, tgt, AembH, AembL);
    k_init_state<<<128,256>>>(h0, c0, cprev, XH, XL);

    // attn_scores = enc @ Wproj^T : [2048,1024]
    gemm3<128,128,32,64,32><<<dim3(16,8),256,SM_LARGE>>>(
        encH, encL, 1024, WprojH, WprojL, 1024, attnS, 1024,
        2048, 1024, 1024, 0,
        nullptr, nullptr, nullptr, nullptr,
        nullptr, nullptr, 0, nullptr, nullptr, 0, nullptr,
        nullptr, nullptr, 0, 0);

    // G_word = emb_gathered @ Wword^T + bias0 : [1536,4096] (permuted gates)
    gemm3<128,128,32,64,32><<<dim3(12,32),256,SM_LARGE>>>(
        AembH, AembL, 512, WwordH, WwordL, 512, Gword, 4096,
        1536, 4096, 512, 1,
        nullptr, bias0, nullptr, nullptr,
        nullptr, nullptr, 0, nullptr, nullptr, 0, nullptr,
        nullptr, nullptr, 0, 0);

    // ---- sequential decode loop ----
    for (int t = 0; t < Tt; t++){
        // gates0 + cell0:  [av | h] @ [Wctx | Whh0]^T + G_word[t]
        gemm3<32,32,32,16,16><<<dim3(1,128),128,SM_SMALL>>>(
            XH, XL, 2048, WcatH, WcatL, 2048, nullptr, 0,
            32, 4096, 2048, 2,
            Gword + (size_t)t*32*4096, nullptr, cprev, cmid,
            HmidH, HmidL, 1024,
            nullptr, nullptr, 0, nullptr,
            nullptr, nullptr, 0, 0);

        // gates1 + cell1:  h_mid @ W1^T + b1
        gemm3<32,32,32,16,16><<<dim3(1,128),128,SM_SMALL>>>(
            HmidH, HmidL, 1024, W1H, W1L, 1024, nullptr, 0,
            32, 4096, 1024, 2,
            nullptr, bias1, cmid, cprev,
            YH, YL, 2048,
            XH + 1024, XL + 1024, 2048, hf32,
            nullptr, nullptr, 0, 0);

        // attention: logits, softmax, context -> Y[:,1024:]
        k_attention<<<32,256>>>(attnS, hf32, src, YH, YL);

        // combine: av = tanh([h|ctx] @ Wcomb^T) -> X[:,0:1024] and AV[t]
        gemm3<32,32,32,16,16><<<dim3(1,32),128,SM_SMALL>>>(
            YH, YL, 2048, WcombH, WcombL, 2048, nullptr, 0,
            32, 1024, 2048, 3,
            nullptr, nullptr, nullptr, nullptr,
            XH, XL, 2048,
            nullptr, nullptr, 0, nullptr,
            AVH, AVL, 1024, t*32);
    }

    // ---- final vocab projection: scores = AV @ Wout^T : [1536, 32000] ----
    gemm3<128,128,32,64,32><<<dim3(12,250),256,SM_LARGE>>>(
        AVH, AVL, 1024, WoutH, WoutL, 1024, out, 32000,
        1536, 32000, 1024, 0,
        nullptr, nullptr, nullptr, nullptr,
        nullptr, nullptr, 0, nullptr, nullptr, 0, nullptr,
        nullptr, nullptr, 0, 0);
}